// round 17
// baseline (speedup 1.0000x reference)
#include <cuda_runtime.h>
#include <cuda_fp16.h>
#include <mma.h>
#include <cstdint>

using namespace nvcuda;

// Problem constants (fixed by the reference)
#define NTOT   2048
#define NGR    32
#define NPG    64
#define C      384
#define G12    12
#define HEFF   2
#define GH     24
#define HD     16

#define XN (NTOT * C)        // 786432
#define WN (C * C)           // 147456

// Scratch (device globals — no allocation allowed)
__device__ __half g_q16[XN];             // q fp16
__device__ __half g_k16[XN];             // k fp16
__device__ __half g_v16[XN];             // v fp16
__device__ __half g_xh[XN];              // x fp16
__device__ __half g_wh[4 * WN];          // Wq | Wk | Wv | Wo fp16
__device__ __half g_ah[XN];              // attention output fp16
__device__ int g_c1[NGR];                // QKV-done counters (9 per graph)
__device__ int g_c2[NGR];                // attn-done counters (3 per graph)

// ---------------------------------------------------------------------------
// cp.async helpers
// ---------------------------------------------------------------------------
__device__ __forceinline__ void cp16(unsigned int dst, const void* src) {
    asm volatile("cp.async.cg.shared.global [%0], [%1], 16;\n" :: "r"(dst), "l"(src));
}
__device__ __forceinline__ void cp_commit() {
    asm volatile("cp.async.commit_group;\n");
}
template <int N>
__device__ __forceinline__ void cp_wait() {
    asm volatile("cp.async.wait_group %0;\n" :: "n"(N));
}

// ---------------------------------------------------------------------------
// One-shot convert: x and the 4 weight matrices -> fp16.
// Block 0 also resets the dataflow counters.
// ---------------------------------------------------------------------------
__global__ __launch_bounds__(256) void split_kernel(
    const float* __restrict__ x,
    const float* __restrict__ wq, const float* __restrict__ wk,
    const float* __restrict__ wv, const float* __restrict__ wo,
    __half* __restrict__ xh, __half* __restrict__ wh)
{
    const int bid = blockIdx.x;
    if (bid == 0 && threadIdx.x < 2 * NGR) {
        if (threadIdx.x < NGR) g_c1[threadIdx.x] = 0;
        else                   g_c2[threadIdx.x - NGR] = 0;
    }
    const float* src;
    __half* dst;
    int loc;
    if (bid < XN / 1024) {
        loc = (bid * 256 + threadIdx.x) * 4;
        src = x; dst = xh;
    } else {
        int w = ((bid - XN / 1024) * 256 + threadIdx.x) * 4;   // [0, 4*WN)
        int m = w / WN;
        loc = w - m * WN;
        src = (m == 0) ? wq : (m == 1) ? wk : (m == 2) ? wv : wo;
        dst = wh + m * WN;
    }
    float4 v4 = *reinterpret_cast<const float4*>(&src[loc]);
    __half2 hp0(__float2half(v4.x), __float2half(v4.y));
    __half2 hp1(__float2half(v4.z), __float2half(v4.w));
    *reinterpret_cast<uint2*>(&dst[loc]) = make_uint2(
        *reinterpret_cast<unsigned*>(&hp0), *reinterpret_cast<unsigned*>(&hp1));
}

// ---------------------------------------------------------------------------
// GEMM tile, pure fp16, BM=64, BN=128, BK=32/iter, 128 threads = 4 warps
// (each warp 32x64 = 2x4 accumulators). 3-stage cp.async ring.
// HALF_OUT: write fp16 (q/k/v); else fp32 (final out). Bias added in fp32.
// ---------------------------------------------------------------------------
#define ASTR 40                      // A smem row stride (elems) = 80B
#define BSTR 136                     // B smem row stride (elems) = 272B
#define AH_O 0
#define BH_O 5120                    // 64 rows * 80B
#define STG_BYTES 13824              // + 32 rows * 272B
#define DSM_BYTES (3 * STG_BYTES)    // 41472

template <bool HALF_OUT>
__device__ __forceinline__ void gemm_tile(
    unsigned char* dsm,
    const __half* __restrict__ Ah, const __half* __restrict__ Bh,
    const float* __restrict__ bias, void* __restrict__ Optr,
    int br, int bc, int K, int N)
{
    const unsigned int sbase = (unsigned int)__cvta_generic_to_shared(dsm);
    const int tid  = threadIdx.x;
    const int warp = tid >> 5;
    const int wr   = warp >> 1;        // 0..1: 32-row band
    const int wc   = warp & 1;         // 0..1: 64-col band
    const int niter = K >> 5;          // 12 for K=384

    // A tile 64x32 fp16 (64B/row): 256 16B-segs, 2/thread. r=s>>2, c=s&3.
    const int ar0 = tid >> 2,           ac0 = (tid & 3) * 16;
    const int ar1 = (tid + 128) >> 2,   ac1 = ((tid + 128) & 3) * 16;

    const __half* agh0 = Ah + (long)(br * 64 + ar0) * K + (ac0 >> 1);
    const __half* agh1 = Ah + (long)(br * 64 + ar1) * K + (ac1 >> 1);
    const unsigned int saa0 = ar0 * (ASTR * 2) + ac0;
    const unsigned int saa1 = ar1 * (ASTR * 2) + ac1;

    // B tile 32x128 fp16 (256B/row): 512 segs, 4/thread. r=s>>4, c=s&15.
    int brr[4], bcc[4];
    const __half* bg[4];
    unsigned int sab[4];
    #pragma unroll
    for (int j = 0; j < 4; j++) {
        int s = tid + j * 128;
        brr[j] = s >> 4; bcc[j] = (s & 15) * 16;
        bg[j] = Bh + (long)brr[j] * N + bc * 128 + (bcc[j] >> 1);
        sab[j] = brr[j] * (BSTR * 2) + bcc[j];
    }

    auto load_stage = [&](int stg, int it) {
        const unsigned sb = sbase + stg * STG_BYTES;
        const int ko = it * 32;
        const long bko = (long)it * 32 * N;
        cp16(sb + AH_O + saa0, agh0 + ko);
        cp16(sb + AH_O + saa1, agh1 + ko);
        #pragma unroll
        for (int j = 0; j < 4; j++)
            cp16(sb + BH_O + sab[j], bg[j] + bko);
        cp_commit();
    };

    load_stage(0, 0);
    load_stage(1, 1);

    wmma::fragment<wmma::accumulator, 16, 16, 16, float> acc[2][4];
    #pragma unroll
    for (int i = 0; i < 2; i++)
        #pragma unroll
        for (int j = 0; j < 4; j++)
            wmma::fill_fragment(acc[i][j], 0.0f);

    for (int it = 0; it < niter; it++) {
        const int s = it % 3;
        if (it + 2 < niter) {
            load_stage((it + 2) % 3, it + 2);
            cp_wait<2>();
        } else if (it + 1 < niter) {
            cp_wait<1>();
        } else {
            cp_wait<0>();
        }
        __syncthreads();

        const __half* ash = reinterpret_cast<const __half*>(dsm + s * STG_BYTES + AH_O);
        const __half* bsh = reinterpret_cast<const __half*>(dsm + s * STG_BYTES + BH_O);

        #pragma unroll
        for (int ks = 0; ks < 2; ks++) {
            const int k16 = ks * 16;
            wmma::fragment<wmma::matrix_a, 16, 16, 16, __half, wmma::row_major> ah[2];
            wmma::fragment<wmma::matrix_b, 16, 16, 16, __half, wmma::row_major> bh[4];
            #pragma unroll
            for (int i = 0; i < 2; i++)
                wmma::load_matrix_sync(ah[i], ash + (wr * 32 + i * 16) * ASTR + k16, ASTR);
            #pragma unroll
            for (int j = 0; j < 4; j++)
                wmma::load_matrix_sync(bh[j], bsh + k16 * BSTR + wc * 64 + j * 16, BSTR);
            #pragma unroll
            for (int i = 0; i < 2; i++)
                #pragma unroll
                for (int j = 0; j < 4; j++)
                    wmma::mma_sync(acc[i][j], ah[i], bh[j], acc[i][j]);
        }
        __syncthreads();
    }

    // Epilogue: acc -> aliased fp32 smem (64x128) -> global (+bias)
    float (*Cs)[128] = reinterpret_cast<float(*)[128]>(dsm);
    #pragma unroll
    for (int i = 0; i < 2; i++)
        #pragma unroll
        for (int j = 0; j < 4; j++)
            wmma::store_matrix_sync(&Cs[wr * 32 + i * 16][wc * 64 + j * 16],
                                    acc[i][j], 128, wmma::mem_row_major);
    __syncthreads();

    #pragma unroll
    for (int l = 0; l < 16; l++) {
        int idx = tid + l * 128;           // 0..2047 4-elem slots
        int r = idx >> 5, c4 = (idx & 31) * 4;
        float4 v = *reinterpret_cast<const float4*>(&Cs[r][c4]);
        const float4 b = *reinterpret_cast<const float4*>(&bias[bc * 128 + c4]);
        v.x += b.x; v.y += b.y; v.z += b.z; v.w += b.w;
        if (HALF_OUT) {
            __half2 h0(__float2half(v.x), __float2half(v.y));
            __half2 h1(__float2half(v.z), __float2half(v.w));
            *reinterpret_cast<uint2*>(
                &reinterpret_cast<__half*>(Optr)[(long)(br * 64 + r) * N + bc * 128 + c4]) =
                make_uint2(*reinterpret_cast<unsigned*>(&h0),
                           *reinterpret_cast<unsigned*>(&h1));
        } else {
            *reinterpret_cast<float4*>(
                &reinterpret_cast<float*>(Optr)[(long)(br * 64 + r) * N + bc * 128 + c4]) = v;
        }
    }
}

// ---------------------------------------------------------------------------
// fp16 row load helper: 16 halves -> 16 floats
// ---------------------------------------------------------------------------
__device__ __forceinline__ void load16h(const __half* p, float* dst) {
    uint4 u0 = reinterpret_cast<const uint4*>(p)[0];
    uint4 u1 = reinterpret_cast<const uint4*>(p)[1];
    const __half2* h0 = reinterpret_cast<const __half2*>(&u0);
    const __half2* h1 = reinterpret_cast<const __half2*>(&u1);
    #pragma unroll
    for (int t = 0; t < 4; t++) {
        float2 f = __half22float2(h0[t]);
        dst[2*t]   = f.x; dst[2*t+1] = f.y;
        float2 g = __half22float2(h1[t]);
        dst[8+2*t]   = g.x; dst[8+2*t+1] = g.y;
    }
}

// ---------------------------------------------------------------------------
// Mega kernel, 384 CTAs of 128 threads:
//   bids [0,288):   QKV GEMM, 9 CTAs/graph (3 mats x 3 col-tiles), fp16 out
//   bids [288,384): fused attention + O GEMM, 3 CTAs/graph:
//       wait QKV(graph) -> 8 group-heads of attention (1 gh/warp, 2 rounds,
//       warp-private smem, no block syncs) -> 3-CTA barrier -> O tile.
// ---------------------------------------------------------------------------
__global__ __launch_bounds__(128, 4) void mega_kernel(
    const float* __restrict__ pos, const float* __restrict__ freqs,
    const float* __restrict__ bq, const float* __restrict__ bk,
    const float* __restrict__ bv, const float* __restrict__ bo,
    float* __restrict__ out)
{
    extern __shared__ __align__(16) unsigned char dsm[];
    const int bid = blockIdx.x;
    const int tid = threadIdx.x;

    if (bid < 288) {
        // ---- QKV projection: 9 CTAs per graph, fp16 outputs ----
        const int g     = bid / 9;
        const int rem   = bid % 9;
        const int which = rem / 3;
        const int bc    = rem % 3;
        const __half* Bh = g_wh + (long)which * WN;
        const float* bias = (which == 0) ? bq : (which == 1) ? bk : bv;
        __half* O = (which == 0) ? g_q16 : (which == 1) ? g_k16 : g_v16;
        gemm_tile<true>(dsm, g_xh, Bh, bias, O, g, bc, C, C);
        __threadfence();
        __syncthreads();
        if (tid == 0) atomicAdd(&g_c1[g], 1);

    } else {
        // ---- Fused attention + O projection: 3 CTAs per graph ----
        const int a    = bid - 288;
        const int g    = a / 3;
        const int c    = a % 3;          // O col-tile AND gh-octet index
        const int warp = tid >> 5;
        const int lane = tid & 31;

        if (tid == 0) {
            while (atomicAdd(&g_c1[g], 0) < 9) __nanosleep(64);
        }
        __syncthreads();
        __threadfence();

        // Warp-private K/V buffers (4 warps x 8KB = 32KB < DSM)
        float (*Ks)[64][16] = reinterpret_cast<float(*)[64][16]>(dsm);
        float (*Vs)[64][16] = reinterpret_cast<float(*)[64][16]>(dsm + 16384);

        #pragma unroll
        for (int round = 0; round < 2; round++) {
            const int gh = c * 8 + round * 4 + warp;   // 0..23
            const int h  = gh & 1;

            float qr[2][16], kr[2][16];
            float p[2][3];
            #pragma unroll
            for (int rr = 0; rr < 2; rr++) {
                const int i    = lane + rr * 32;
                const int node = g * NPG + i;
                const int off  = node * C + gh * HD;
                load16h(g_q16 + off, qr[rr]);
                load16h(g_k16 + off, kr[rr]);
                float vv[16];
                load16h(g_v16 + off, vv);
                #pragma unroll
                for (int d = 0; d < 16; d++) Vs[warp][i][d] = vv[d];
                p[rr][0] = pos[node * 3 + 0];
                p[rr][1] = pos[node * 3 + 1];
                p[rr][2] = pos[node * 3 + 2];
            }

            #pragma unroll
            for (int rr = 0; rr < 2; rr++) {
                #pragma unroll
                for (int f = 0; f < 8; f++) {
                    float th = p[rr][0] * freqs[ 0 + h * 8 + f]
                             + p[rr][1] * freqs[16 + h * 8 + f]
                             + p[rr][2] * freqs[32 + h * 8 + f];
                    float s, cc;
                    __sincosf(th, &s, &cc);
                    float q1 = qr[rr][2*f], q2 = qr[rr][2*f+1];
                    qr[rr][2*f]   = q1 * cc - q2 * s;
                    qr[rr][2*f+1] = q1 * s + q2 * cc;
                    float k1 = kr[rr][2*f], k2 = kr[rr][2*f+1];
                    kr[rr][2*f]   = k1 * cc - k2 * s;
                    kr[rr][2*f+1] = k1 * s + k2 * cc;
                }
                #pragma unroll
                for (int d = 0; d < 16; d++) qr[rr][d] *= 0.25f;
                #pragma unroll
                for (int d = 0; d < 16; d++) Ks[warp][lane + rr * 32][d] = kr[rr][d];
            }
            __syncwarp();

            float den[2] = {0.f, 0.f};
            float o0[16] = {}, o1[16] = {};
            #pragma unroll 2
            for (int j = 0; j < 64; j++) {
                float s0 = 0.f, s1 = 0.f;
                #pragma unroll
                for (int d = 0; d < 16; d++) {
                    float kv = Ks[warp][j][d];
                    s0 = fmaf(qr[0][d], kv, s0);
                    s1 = fmaf(qr[1][d], kv, s1);
                }
                float e0 = __expf(s0), e1 = __expf(s1);
                den[0] += e0; den[1] += e1;
                #pragma unroll
                for (int d = 0; d < 16; d++) {
                    float vv = Vs[warp][j][d];
                    o0[d] = fmaf(e0, vv, o0[d]);
                    o1[d] = fmaf(e1, vv, o1[d]);
                }
            }

            #pragma unroll
            for (int rr = 0; rr < 2; rr++) {
                const float inv = 1.f / den[rr];
                const float* o = (rr == 0) ? o0 : o1;
                const int node = g * NPG + lane + rr * 32;
                const int off  = node * C + gh * HD;
                __half hb[16];
                #pragma unroll
                for (int d = 0; d < 16; d++) hb[d] = __float2half(o[d] * inv);
                uint4 uh0, uh1;
                unsigned* uhp0 = &uh0.x; unsigned* uhp1 = &uh1.x;
                #pragma unroll
                for (int t = 0; t < 4; t++) {
                    __half2 a2(hb[2*t], hb[2*t+1]);      uhp0[t] = *reinterpret_cast<unsigned*>(&a2);
                    __half2 b2(hb[8+2*t], hb[8+2*t+1]);  uhp1[t] = *reinterpret_cast<unsigned*>(&b2);
                }
                uint4* ahp = reinterpret_cast<uint4*>(&g_ah[off]);
                ahp[0] = uh0; ahp[1] = uh1;
            }
            __syncwarp();
        }

        // 3-CTA barrier: all 24 gh of this graph must be in g_ah
        __threadfence();
        __syncthreads();
        if (tid == 0) {
            atomicAdd(&g_c2[g], 1);
            while (atomicAdd(&g_c2[g], 0) < 3) __nanosleep(64);
        }
        __syncthreads();
        __threadfence();

        // O projection tile (row-tile = graph, col-tile = c)
        gemm_tile<false>(dsm, g_ah, g_wh + 3L * WN, bo, out, g, c, C, C);
    }
}

// ---------------------------------------------------------------------------
extern "C" void kernel_launch(void* const* d_in, const int* in_sizes, int n_in,
                              void* d_out, int out_size)
{
    const float* x     = (const float*)d_in[0];
    const float* pos   = (const float*)d_in[1];
    const float* Wq    = (const float*)d_in[2];
    const float* bq    = (const float*)d_in[3];
    const float* Wk    = (const float*)d_in[4];
    const float* bk    = (const float*)d_in[5];
    const float* Wv    = (const float*)d_in[6];
    const float* bv    = (const float*)d_in[7];
    const float* Wo    = (const float*)d_in[8];
    const float* bo    = (const float*)d_in[9];
    const float* rfreq = (const float*)d_in[10];
    float* out = (float*)d_out;

    __half *xh, *wh;
    cudaGetSymbolAddress((void**)&xh, g_xh);
    cudaGetSymbolAddress((void**)&wh, g_wh);

    cudaFuncSetAttribute(mega_kernel,
                         cudaFuncAttributeMaxDynamicSharedMemorySize, DSM_BYTES);

    // 1) Convert x and weights to fp16 + reset dataflow counters
    int nblk = XN / 1024 + 4 * WN / 1024;     // 1344
    split_kernel<<<nblk, 256>>>(x, Wq, Wk, Wv, Wo, xh, wh);

    // 2) Fused QKV + (attention + O-projection), single-wave dataflow
    mega_kernel<<<384, 128, DSM_BYTES>>>(pos, rfreq, bq, bk, bv, bo, out);
}